// round 4
// baseline (speedup 1.0000x reference)
#include <cuda_runtime.h>
#include <cstdint>

// Problem constants (from reference): C=1000, N=256, D=512, B=4096
#define CC 1000
#define NN 256
#define DD 512
#define BB 4096

#define ROWS_PER_BLOCK 16         // gather: 16 rows * 2KB = 32KB per block
#define GATHER_THREADS 256        // 8 warps, 2 rows per warp, 8 float4/thread

#define FUSED_BLOCKS 1000
#define FUSED_THREADS 256

// Scratch (no allocations allowed). Static zero-init: 0 means "no push".
__device__ int g_last_pos1[CC];     // last valid batch pos + 1 per class; 0 = none
__device__ int g_src[CC * NN];      // global source row per output row:
                                    //   >=0 : row index into memory  [C*N)
                                    //   <0  : ~idx = row index into batch_features
__device__ unsigned g_arrive;       // barrier arrivals (self-resets each launch)
__device__ unsigned g_release;      // barrier phase (monotonic across launches)

// ---------------------------------------------------------------------------
// Software grid barrier. Safe ONLY because the launch is a guaranteed single
// wave: __launch_bounds__(256, 8) -> 8 blocks/SM resident -> 148*8 = 1184
// slots >= 1000 blocks, so every block is running before any block spins.
__device__ __forceinline__ void grid_barrier() {
    __syncthreads();
    if (threadIdx.x == 0) {
        unsigned phase = *(volatile unsigned*)&g_release;
        __threadfence();
        unsigned old = atomicAdd(&g_arrive, 1u);
        if (old == (unsigned)(gridDim.x - 1)) {
            g_arrive = 0;                 // reset for next graph replay
            __threadfence();
            atomicExch(&g_release, phase + 1u);
        } else {
            while (*(volatile unsigned*)&g_release == phase) { }
        }
        __threadfence();
    }
    __syncthreads();
}

// ---------------------------------------------------------------------------
// Fused kernel.
// Phase 1 (select): one warp per batch item. First-occurrence argmax over the
//   int32 targets row (values tiny, ties common -> must keep FIRST max),
//   validity check vs ORIGINAL last-slot confidence, atomicMax(pos+1).
// Grid barrier.
// Phase 2 (sort): block c sorts class c's conf2 (only slot N-1 replaced when
//   updated) with a stable-descending u64 bitonic sort, emits global source
//   rows into g_src, and resets g_last_pos1[c] for the next replay.
__global__ void __launch_bounds__(FUSED_THREADS, 8)
k_fused(const int*   __restrict__ tgt,
        const float* __restrict__ bconf,
        const int*   __restrict__ mask,
        const float* __restrict__ conf) {
    const int t    = threadIdx.x;
    const int warp = t >> 5;
    const int lane = t & 31;

    // ---------------- Phase 1: select ----------------
    int item = blockIdx.x * (FUSED_THREADS / 32) + warp;
    if (item < BB && mask[item] != 0) {
        const int4* row = (const int4*)(tgt + (long long)item * CC);  // 250 int4
        int bestv = -2147483647 - 1;
        int besti = CC;
        // per-lane traversal is in increasing index order -> strict '>' keeps
        // the first occurrence of the max
        for (int j = lane; j < CC / 4; j += 32) {
            int4 q = row[j];
            int base = j * 4;
            if (q.x > bestv) { bestv = q.x; besti = base;     }
            if (q.y > bestv) { bestv = q.y; besti = base + 1; }
            if (q.z > bestv) { bestv = q.z; besti = base + 2; }
            if (q.w > bestv) { bestv = q.w; besti = base + 3; }
        }
        #pragma unroll
        for (int off = 16; off; off >>= 1) {
            int ov = __shfl_down_sync(0xffffffffu, bestv, off);
            int oi = __shfl_down_sync(0xffffffffu, besti, off);
            if (ov > bestv || (ov == bestv && oi < besti)) { bestv = ov; besti = oi; }
        }
        if (lane == 0) {
            int tc = besti;
            if (bconf[item] > conf[tc * NN + (NN - 1)]) {
                atomicMax(&g_last_pos1[tc], item + 1);
            }
        }
    }

    // ---------------- barrier ----------------
    grid_barrier();

    // ---------------- Phase 2: per-class sort ----------------
    int c = blockIdx.x;
    if (c >= CC) return;

    __shared__ unsigned long long key[NN];

    int lp1 = g_last_pos1[c];
    bool updated = (lp1 > 0);
    int lp = lp1 - 1;

    float v = (updated && t == NN - 1) ? bconf[lp] : conf[c * NN + t];
    // order-preserving float->uint (ascending), then invert for descending
    unsigned u = __float_as_uint(v);
    u = (u & 0x80000000u) ? ~u : (u | 0x80000000u);
    unsigned inv = ~u;
    key[t] = ((unsigned long long)inv << 32) | (unsigned)t;
    __syncthreads();

    // all threads have read g_last_pos1[c]; reset for the next graph replay
    if (t == 0) g_last_pos1[c] = 0;

    // ascending bitonic sort of 256 u64 keys (desc conf, asc slot index ==
    // exactly the stable argsort(-conf) of the reference)
    for (int k = 2; k <= NN; k <<= 1) {
        for (int j = k >> 1; j > 0; j >>= 1) {
            int ixj = t ^ j;
            if (ixj > t) {
                bool up = ((t & k) == 0);
                unsigned long long a = key[t], b = key[ixj];
                if ((a > b) == up) { key[t] = b; key[ixj] = a; }
            }
            __syncthreads();
        }
    }

    int slot = (int)(key[t] & 0xffffffffu);   // pre-shift slot whose conf sorts here
    int src;
    if (updated) {
        if (slot == NN - 1) src = ~lp;                 // new feature from batch
        else                src = c * NN + slot + 1;   // shifted memory row
    } else {
        src = c * NN + slot;
    }
    g_src[c * NN + t] = src;
}

// ---------------------------------------------------------------------------
// Gather: 16 rows per block, 8 warps, each warp owns 2 rows.
// 8 independent float4 loads front-batched, then 8 stores. Streaming hints.
__global__ void __launch_bounds__(GATHER_THREADS)
k_gather(const float* __restrict__ mem,
         const float* __restrict__ bfeat,
         float* __restrict__ out) {
    const int t    = threadIdx.x;
    const int warp = t >> 5;
    const int lane = t & 31;
    const long long row0 = (long long)blockIdx.x * ROWS_PER_BLOCK + warp * 2;

    int s0 = g_src[row0];
    int s1 = g_src[row0 + 1];
    const float4* a = (const float4*)((s0 >= 0) ? mem   + (long long)s0    * DD
                                                : bfeat + (long long)(~s0) * DD);
    const float4* b = (const float4*)((s1 >= 0) ? mem   + (long long)s1    * DD
                                                : bfeat + (long long)(~s1) * DD);
    float4 v[8];
    #pragma unroll
    for (int p = 0; p < 4; p++) v[p]     = __ldcs(a + lane + p * 32);
    #pragma unroll
    for (int p = 0; p < 4; p++) v[4 + p] = __ldcs(b + lane + p * 32);

    float4* o = (float4*)out + row0 * (DD / 4);
    #pragma unroll
    for (int p = 0; p < 4; p++) __stcs(o + lane + p * 32, v[p]);
    #pragma unroll
    for (int p = 0; p < 4; p++) __stcs(o + (DD / 4) + lane + p * 32, v[4 + p]);
}

// ---------------------------------------------------------------------------
extern "C" void kernel_launch(void* const* d_in, const int* in_sizes, int n_in,
                              void* d_out, int out_size) {
    const float* batch_features    = (const float*)d_in[0];   // [B, D]
    const int*   batch_targets     = (const int*)  d_in[1];   // [B, C] int32
    const float* batch_confidences = (const float*)d_in[2];   // [B]
    const int*   selected_mask     = (const int*)  d_in[3];   // [B]
    const float* memory            = (const float*)d_in[4];   // [C, N, D]
    const float* confidences       = (const float*)d_in[5];   // [C, N]
    float* out = (float*)d_out;                               // [C, N, D]

    k_fused<<<FUSED_BLOCKS, FUSED_THREADS>>>(batch_targets, batch_confidences,
                                             selected_mask, confidences);
    k_gather<<<(CC * NN) / ROWS_PER_BLOCK, GATHER_THREADS>>>(memory, batch_features, out);
}

// round 5
// speedup vs baseline: 1.0124x; 1.0124x over previous
#include <cuda_runtime.h>
#include <cstdint>

// Problem constants (from reference): C=1000, N=256, D=512, B=4096
#define CC 1000
#define NN 256
#define DD 512
#define BB 4096

#define ROWS_PER_BLOCK 16         // gather: 16 rows * 2KB = 32KB per block
#define GATHER_THREADS 256        // 8 warps, 2 rows per warp, 8 float4/thread

// Scratch (no allocations allowed). Static zero-init: 0 means "no push".
__device__ int g_last_pos1[CC];   // last valid batch pos + 1 per class; 0 = none
__device__ int g_src[CC * NN];    // global source row per output row:
                                  //   >=0 : row index into memory  [C*N)
                                  //   <0  : ~idx = row index into batch_features

// ---------------------------------------------------------------------------
// Kernel 1: one BLOCK per batch item. 256 threads; thread t loads int4 #t of
// the item's 1000-int target row (250 int4 total), so the entire row is in
// flight at once. First-occurrence argmax (value desc, index asc), validity
// check vs ORIGINAL last-slot confidence, atomicMax(pos+1) for last-write-wins.
__global__ void __launch_bounds__(256)
k_select(const int*   __restrict__ tgt,
         const float* __restrict__ bconf,
         const int*   __restrict__ mask,
         const float* __restrict__ conf) {
    const int item = blockIdx.x;
    if (mask[item] == 0) return;

    const int t    = threadIdx.x;
    const int warp = t >> 5;
    const int lane = t & 31;

    int bestv = -2147483647 - 1;
    int besti = CC;
    if (t < CC / 4) {
        int4 q = ((const int4*)(tgt + (long long)item * CC))[t];
        int base = t * 4;
        // ascending order within the quad -> strict '>' keeps first occurrence
        bestv = q.x; besti = base;
        if (q.y > bestv) { bestv = q.y; besti = base + 1; }
        if (q.z > bestv) { bestv = q.z; besti = base + 2; }
        if (q.w > bestv) { bestv = q.w; besti = base + 3; }
    }
    // warp reduce: value desc, index asc
    #pragma unroll
    for (int off = 16; off; off >>= 1) {
        int ov = __shfl_down_sync(0xffffffffu, bestv, off);
        int oi = __shfl_down_sync(0xffffffffu, besti, off);
        if (ov > bestv || (ov == bestv && oi < besti)) { bestv = ov; besti = oi; }
    }
    __shared__ int sv[8], si[8];
    if (lane == 0) { sv[warp] = bestv; si[warp] = besti; }
    __syncthreads();
    if (t == 0) {
        int bv = sv[0], bi = si[0];
        #pragma unroll
        for (int w = 1; w < 8; w++) {
            if (sv[w] > bv || (sv[w] == bv && si[w] < bi)) { bv = sv[w]; bi = si[w]; }
        }
        // validity vs ORIGINAL last-slot confidence of the class
        if (bconf[item] > conf[bi * NN + (NN - 1)]) {
            atomicMax(&g_last_pos1[bi], item + 1);
        }
    }
}

// ---------------------------------------------------------------------------
// Kernel 2: per class, build conf2 (only slot N-1 replaced when updated),
// stable descending argsort via u64 bitonic sort (desc conf, asc index),
// emit per-output-row GLOBAL source row (post-shift mapping).
// Also resets g_last_pos1[c] to 0 so every graph replay starts clean.
__global__ void k_sort(const float* __restrict__ conf,
                       const float* __restrict__ bconf) {
    int c = blockIdx.x;
    int t = threadIdx.x;   // 256 threads, one per slot
    __shared__ unsigned long long key[NN];

    int lp1 = g_last_pos1[c];
    bool updated = (lp1 > 0);
    int lp = lp1 - 1;

    float v = (updated && t == NN - 1) ? bconf[lp] : conf[c * NN + t];
    // order-preserving float->uint (ascending), then invert for descending
    unsigned u = __float_as_uint(v);
    u = (u & 0x80000000u) ? ~u : (u | 0x80000000u);
    unsigned inv = ~u;
    key[t] = ((unsigned long long)inv << 32) | (unsigned)t;
    __syncthreads();

    // all threads have read g_last_pos1[c]; reset for the next graph replay
    if (t == 0) g_last_pos1[c] = 0;

    // ascending bitonic sort of 256 u64 keys (desc conf, asc slot index ==
    // exactly the stable argsort(-conf) of the reference)
    for (int k = 2; k <= NN; k <<= 1) {
        for (int j = k >> 1; j > 0; j >>= 1) {
            int ixj = t ^ j;
            if (ixj > t) {
                bool up = ((t & k) == 0);
                unsigned long long a = key[t], b = key[ixj];
                if ((a > b) == up) { key[t] = b; key[ixj] = a; }
            }
            __syncthreads();
        }
    }

    int slot = (int)(key[t] & 0xffffffffu);   // pre-shift slot whose conf sorts here
    int src;
    if (updated) {
        if (slot == NN - 1) src = ~lp;                 // new feature from batch
        else                src = c * NN + slot + 1;   // shifted memory row
    } else {
        src = c * NN + slot;
    }
    g_src[c * NN + t] = src;
}

// ---------------------------------------------------------------------------
// Kernel 3: gather rows. 16 rows per block, 8 warps, each warp owns 2 rows.
// 8 independent float4 loads front-batched, then 8 stores. Streaming hints:
// data is use-once. Converged at ~85% DRAM (mixed R/W ceiling).
__global__ void __launch_bounds__(GATHER_THREADS)
k_gather(const float* __restrict__ mem,
         const float* __restrict__ bfeat,
         float* __restrict__ out) {
    const int t    = threadIdx.x;
    const int warp = t >> 5;
    const int lane = t & 31;
    const long long row0 = (long long)blockIdx.x * ROWS_PER_BLOCK + warp * 2;

    int s0 = g_src[row0];
    int s1 = g_src[row0 + 1];
    const float4* a = (const float4*)((s0 >= 0) ? mem   + (long long)s0    * DD
                                                : bfeat + (long long)(~s0) * DD);
    const float4* b = (const float4*)((s1 >= 0) ? mem   + (long long)s1    * DD
                                                : bfeat + (long long)(~s1) * DD);
    float4 v[8];
    #pragma unroll
    for (int p = 0; p < 4; p++) v[p]     = __ldcs(a + lane + p * 32);
    #pragma unroll
    for (int p = 0; p < 4; p++) v[4 + p] = __ldcs(b + lane + p * 32);

    float4* o = (float4*)out + row0 * (DD / 4);
    #pragma unroll
    for (int p = 0; p < 4; p++) __stcs(o + lane + p * 32, v[p]);
    #pragma unroll
    for (int p = 0; p < 4; p++) __stcs(o + (DD / 4) + lane + p * 32, v[4 + p]);
}

// ---------------------------------------------------------------------------
extern "C" void kernel_launch(void* const* d_in, const int* in_sizes, int n_in,
                              void* d_out, int out_size) {
    const float* batch_features    = (const float*)d_in[0];   // [B, D]
    const int*   batch_targets     = (const int*)  d_in[1];   // [B, C] int32
    const float* batch_confidences = (const float*)d_in[2];   // [B]
    const int*   selected_mask     = (const int*)  d_in[3];   // [B]
    const float* memory            = (const float*)d_in[4];   // [C, N, D]
    const float* confidences       = (const float*)d_in[5];   // [C, N]
    float* out = (float*)d_out;                               // [C, N, D]

    k_select<<<BB, 256>>>(batch_targets, batch_confidences,
                          selected_mask, confidences);
    k_sort<<<CC, NN>>>(confidences, batch_confidences);
    k_gather<<<(CC * NN) / ROWS_PER_BLOCK, GATHER_THREADS>>>(memory, batch_features, out);
}